// round 2
// baseline (speedup 1.0000x reference)
#include <cuda_runtime.h>
#include <math.h>

#define BATCH 16384
#define DIM 64
#define LAMBDA 0.01f
#define R 2                      // rows per 16-lane group
#define TPB 256                  // 16 groups per block
#define ROWS_PER_BLOCK (16 * R)  // 32
#define GRID (BATCH / ROWS_PER_BLOCK)  // 512

__device__ float        g_scratch = 0.0f;
__device__ unsigned int g_count   = 0;

__global__ void __launch_bounds__(TPB) pmf_kernel(
    const int* __restrict__ u,
    const int* __restrict__ iidx,
    const int* __restrict__ s,
    const float4* __restrict__ W4,   // [USER_SIZE * 16]
    const float4* __restrict__ H4,   // [ITEM_SIZE * 16]
    float* __restrict__ out)
{
    const int tid  = threadIdx.x;
    const int grp  = tid >> 4;          // 0..15
    const int lane = tid & 15;          // 0..15
    const int base = (blockIdx.x * 16 + grp) * R;   // first row for this group

    // ---- batch all index loads, then all table loads (max MLP) ----
    int ur[R], ir[R];
    #pragma unroll
    for (int r = 0; r < R; r++) {
        ur[r] = __ldg(&u[base + r]);
        ir[r] = __ldg(&iidx[base + r]);
    }

    float4 a[R], b[R];
    #pragma unroll
    for (int r = 0; r < R; r++)
        a[r] = __ldg(&W4[(size_t)ur[r] * 16 + lane]);
    #pragma unroll
    for (int r = 0; r < R; r++)
        b[r] = __ldg(&H4[(size_t)ir[r] * 16 + lane]);

    // ---- per-row dot + reg, reduced across the 16-lane group ----
    float contrib = 0.0f;   // valid only on lane 0 of each group
    #pragma unroll
    for (int r = 0; r < R; r++) {
        float dot = a[r].x * b[r].x + a[r].y * b[r].y
                  + a[r].z * b[r].z + a[r].w * b[r].w;
        float reg = LAMBDA * (a[r].x * a[r].x + a[r].y * a[r].y
                            + a[r].z * a[r].z + a[r].w * a[r].w
                            + b[r].x * b[r].x + b[r].y * b[r].y
                            + b[r].z * b[r].z + b[r].w * b[r].w);
        #pragma unroll
        for (int off = 8; off >= 1; off >>= 1) {
            dot += __shfl_down_sync(0xFFFFFFFFu, dot, off);
            reg += __shfl_down_sync(0xFFFFFFFFu, reg, off);
        }
        if (lane == 0) {
            float x  = dot;
            float ls = fminf(x, 0.0f) - log1pf(expf(-fabsf(x)));
            float d  = (float)__ldg(&s[base + r]) - ls;
            contrib += d * d + reg;
        }
    }

    // ---- block reduction ----
    __shared__ float sdata[16];
    if (lane == 0) sdata[grp] = contrib;
    __syncthreads();

    if (tid < 16) {
        float v = sdata[tid];
        #pragma unroll
        for (int off = 8; off >= 1; off >>= 1)
            v += __shfl_down_sync(0xFFFFu, v, off);
        if (tid == 0)
            atomicAdd(&g_scratch, v);
    }

    // ---- last block writes result and resets scratch (graph-replayable) ----
    __shared__ bool is_last;
    __threadfence();
    if (tid == 0) {
        unsigned int done = atomicAdd(&g_count, 1u);
        is_last = (done == (unsigned int)(gridDim.x - 1));
    }
    __syncthreads();
    if (is_last && tid == 0) {
        float total = atomicExch(&g_scratch, 0.0f);  // read + reset for next replay
        g_count = 0;
        out[0] = total * (1.0f / (float)BATCH);
    }
}

extern "C" void kernel_launch(void* const* d_in, const int* in_sizes, int n_in,
                              void* d_out, int out_size) {
    const int*   u = (const int*)d_in[0];
    const int*   i = (const int*)d_in[1];
    const int*   s = (const int*)d_in[2];
    const float* W = (const float*)d_in[3];
    const float* H = (const float*)d_in[4];
    float* out = (float*)d_out;

    pmf_kernel<<<GRID, TPB>>>(u, i, s,
                              (const float4*)W, (const float4*)H, out);
}

// round 3
// speedup vs baseline: 1.0257x; 1.0257x over previous
#include <cuda_runtime.h>
#include <math.h>

#define BATCH 16384
#define DIM 64
#define LAMBDA 0.01f
#define TPB 256
#define GRID (BATCH / 16)   // 1024 blocks, 16 rows per block (one per 16-lane group)

__device__ float        g_scratch = 0.0f;
__device__ unsigned int g_count   = 0;

__global__ void __launch_bounds__(TPB) pmf_kernel(
    const int* __restrict__ u,
    const int* __restrict__ iidx,
    const int* __restrict__ s,
    const float4* __restrict__ W4,   // [USER_SIZE * 16]
    const float4* __restrict__ H4,   // [ITEM_SIZE * 16]
    float* __restrict__ out)
{
    const int tid  = threadIdx.x;
    const int grp  = tid >> 4;          // 0..15
    const int lane = tid & 15;          // 0..15
    const int row  = blockIdx.x * 16 + grp;

    const int ur = __ldg(&u[row]);
    const int ir = __ldg(&iidx[row]);

    // two independent 16B gathers per thread (MLP=2)
    const float4 a = __ldg(&W4[(size_t)ur * 16 + lane]);
    const float4 b = __ldg(&H4[(size_t)ir * 16 + lane]);

    float dot = a.x * b.x + a.y * b.y + a.z * b.z + a.w * b.w;
    float reg = LAMBDA * (a.x * a.x + a.y * a.y + a.z * a.z + a.w * a.w
                        + b.x * b.x + b.y * b.y + b.z * b.z + b.w * b.w);

    #pragma unroll
    for (int off = 8; off >= 1; off >>= 1) {
        dot += __shfl_down_sync(0xFFFFFFFFu, dot, off);
        reg += __shfl_down_sync(0xFFFFFFFFu, reg, off);
    }

    __shared__ float sdata[16];
    if (lane == 0) {
        float x  = dot;
        float ls = fminf(x, 0.0f) - log1pf(expf(-fabsf(x)));   // stable log-sigmoid
        float d  = (float)__ldg(&s[row]) - ls;
        sdata[grp] = d * d + reg;
    }
    __syncthreads();

    if (tid < 16) {
        float v = sdata[tid];
        #pragma unroll
        for (int off = 8; off >= 1; off >>= 1)
            v += __shfl_down_sync(0xFFFFu, v, off);
        if (tid == 0)
            atomicAdd(&g_scratch, v);
    }

    // ---- last block folds the total into d_out and resets scratch ----
    __shared__ bool is_last;
    __threadfence();
    if (tid == 0) {
        unsigned int done = atomicAdd(&g_count, 1u);
        is_last = (done == (unsigned int)(gridDim.x - 1));
    }
    __syncthreads();
    if (is_last && tid == 0) {
        float total = atomicExch(&g_scratch, 0.0f);   // read + reset for graph replay
        g_count = 0;
        out[0] = total * (1.0f / (float)BATCH);
    }
}

extern "C" void kernel_launch(void* const* d_in, const int* in_sizes, int n_in,
                              void* d_out, int out_size) {
    const int*   u = (const int*)d_in[0];
    const int*   i = (const int*)d_in[1];
    const int*   s = (const int*)d_in[2];
    const float* W = (const float*)d_in[3];
    const float* H = (const float*)d_in[4];
    float* out = (float*)d_out;

    pmf_kernel<<<GRID, TPB>>>(u, i, s,
                              (const float4*)W, (const float4*)H, out);
}